// round 8
// baseline (speedup 1.0000x reference)
#include <cuda_runtime.h>
#include <cuda_bf16.h>
#include <cfloat>

#define BATCH 4
#define NPTS 4096
#define NUP 16384
#define CDIM 64
#define EPSV 1e-6f

// Spatial grid: [-5,5]^3, h=0.25
#define GDIM 40
#define GCELLS (GDIM * GDIM * GDIM)     // 64000
#define TOTCELLS (BATCH * GCELLS)       // 256000
#define GLO (-5.0f)
#define GH 0.25f
#define GINV 4.0f
#define SCANB (TOTCELLS / 1024)         // 250

// Scratch (__device__ globals; no cudaMalloc allowed)
__device__ float  g_G[BATCH * NPTS * CDIM];     // projected features F@W+b (4 MB)
__device__ int    g_cnt2[2][TOTCELLS];          // histograms: [0]=points [1]=queries
__device__ int    g_start2[2][TOTCELLS + 1];    // exclusive scans
__device__ int    g_cur2[2][TOTCELLS];          // scatter cursors
__device__ int    g_bsum2[2][256];              // block sums
__device__ float4 g_tpos[BATCH * NPTS];         // staged point (x,y,z,|p|^2)
__device__ int    g_tcell[BATCH * NPTS];
__device__ float4 g_qpos[BATCH * NUP];          // staged query (x,y,z,|q|^2)
__device__ int    g_qcell[BATCH * NUP];
__device__ float4 g_spos[BATCH * NPTS];         // cell-sorted points
__device__ int    g_sidx[BATCH * NPTS];         // sorted -> original local idx
__device__ float4 g_sqpos[BATCH * NUP];         // cell-sorted queries
__device__ int    g_sqid[BATCH * NUP];          // sorted -> original global qid
__device__ float4 g_w3[BATCH * NUP];            // normalized weights (by orig qid)
__device__ int4   g_j3[BATCH * NUP];            // neighbor orig indices (by orig qid)

__device__ __forceinline__ int cell_coord(float v) {
    int c = (int)floorf((v - GLO) * GINV);
    return min(max(c, 0), GDIM - 1);
}

// ---------------------------------------------------------------------------
// K0: zero both histograms
// ---------------------------------------------------------------------------
__global__ void zero_cnt_kernel() {
    int i = blockIdx.x * blockDim.x + threadIdx.x;     // 128000 threads
    reinterpret_cast<int4*>(&g_cnt2[0][0])[i] = make_int4(0, 0, 0, 0);
}

// ---------------------------------------------------------------------------
// K1: histogram + stage for BOTH points (blocks [0,64)) and queries [64,320)
// ---------------------------------------------------------------------------
__global__ void hist_both_kernel(const float* __restrict__ pos,
                                 const float* __restrict__ pos_up) {
    int t = blockIdx.x * 256 + threadIdx.x;
    if (blockIdx.x < 64) {                 // points
        int i = t;
        int b = i >> 12;
        float x = pos[3 * i + 0];
        float y = pos[3 * i + 1];
        float z = pos[3 * i + 2];
        float n = x * x + y * y + z * z;
        g_tpos[i] = make_float4(x, y, z, n);
        int cell = b * GCELLS + ((cell_coord(z) * GDIM) + cell_coord(y)) * GDIM + cell_coord(x);
        g_tcell[i] = cell;
        atomicAdd(&g_cnt2[0][cell], 1);
    } else {                               // queries
        int i = t - 16384;
        int b = i >> 14;
        float x = pos_up[3 * i + 0];
        float y = pos_up[3 * i + 1];
        float z = pos_up[3 * i + 2];
        float n = x * x + y * y + z * z;
        g_qpos[i] = make_float4(x, y, z, n);
        int cell = b * GCELLS + ((cell_coord(z) * GDIM) + cell_coord(y)) * GDIM + cell_coord(x);
        g_qcell[i] = cell;
        atomicAdd(&g_cnt2[1][cell], 1);
    }
}

// ---------------------------------------------------------------------------
// K2a/b/c: exclusive scans of both histograms
// ---------------------------------------------------------------------------
__device__ __forceinline__ int block_exscan_1024(int v, int* ws) {
    int lane = threadIdx.x & 31, w = threadIdx.x >> 5;
    int inc = v;
#pragma unroll
    for (int o = 1; o < 32; o <<= 1) {
        int n = __shfl_up_sync(0xffffffffu, inc, o);
        if (lane >= o) inc += n;
    }
    if (lane == 31) ws[w] = inc;
    __syncthreads();
    if (w == 0) {
        int t = ws[lane];
#pragma unroll
        for (int o = 1; o < 32; o <<= 1) {
            int n = __shfl_up_sync(0xffffffffu, t, o);
            if (lane >= o) t += n;
        }
        ws[lane] = t;
    }
    __syncthreads();
    return inc - v + (w > 0 ? ws[w - 1] : 0);
}

__global__ __launch_bounds__(1024) void scan_a_kernel() {   // grid 500
    __shared__ int ws[32];
    int ab = blockIdx.x >= SCANB;
    int blk = blockIdx.x - ab * SCANB;
    int g = blk * 1024 + threadIdx.x;
    int v = g_cnt2[ab][g];
    int ex = block_exscan_1024(v, ws);
    g_start2[ab][g] = ex;
    if (threadIdx.x == 1023) g_bsum2[ab][blk] = ex + v;
}

__global__ __launch_bounds__(1024) void scan_b_kernel() {   // grid 2
    __shared__ int ws[32];
    int ab = blockIdx.x;
    int v = (threadIdx.x < SCANB) ? g_bsum2[ab][threadIdx.x] : 0;
    int ex = block_exscan_1024(v, ws);
    if (threadIdx.x < SCANB) g_bsum2[ab][threadIdx.x] = ex;
}

__global__ __launch_bounds__(1024) void scan_c_kernel() {   // grid 500
    int ab = blockIdx.x >= SCANB;
    int blk = blockIdx.x - ab * SCANB;
    int g = blk * 1024 + threadIdx.x;
    int s = g_start2[ab][g] + g_bsum2[ab][blk];
    g_start2[ab][g] = s;
    g_cur2[ab][g] = s;
    if (g == TOTCELLS - 1)
        g_start2[ab][TOTCELLS] = ab ? (BATCH * NUP) : (BATCH * NPTS);
}

// ---------------------------------------------------------------------------
// K3: scatter both into cell-sorted order
// ---------------------------------------------------------------------------
__global__ void scatter_both_kernel() {
    int t = blockIdx.x * 256 + threadIdx.x;
    if (blockIdx.x < 64) {
        int i = t;
        int dst = atomicAdd(&g_cur2[0][g_tcell[i]], 1);
        g_spos[dst] = g_tpos[i];
        g_sidx[dst] = i & (NPTS - 1);
    } else {
        int i = t - 16384;
        int dst = atomicAdd(&g_cur2[1][g_qcell[i]], 1);
        g_sqpos[dst] = g_qpos[i];
        g_sqid[dst] = i;
    }
}

// ---------------------------------------------------------------------------
// K4: projection G = F @ W + b
// ---------------------------------------------------------------------------
#define PROJ_ROWS 32

__global__ __launch_bounds__(64) void proj_kernel(
    const float* __restrict__ feature,
    const float* __restrict__ W,
    const float* __restrict__ bias)
{
    __shared__ float frow[PROJ_ROWS * CDIM];
    const int d = threadIdx.x;
    const int row0 = blockIdx.x * PROJ_ROWS;

    float wcol[CDIM];
#pragma unroll
    for (int k = 0; k < CDIM; k++) wcol[k] = __ldg(&W[k * CDIM + d]);
    const float bd = __ldg(&bias[d]);

    const float* fsrc = feature + (size_t)row0 * CDIM;
    for (int i = threadIdx.x; i < PROJ_ROWS * CDIM; i += 64)
        frow[i] = fsrc[i];
    __syncthreads();

    for (int r = 0; r < PROJ_ROWS; r++) {
        float a0 = bd, a1 = 0.f, a2 = 0.f, a3 = 0.f;
        const float* fr = &frow[r * CDIM];
#pragma unroll
        for (int k = 0; k < CDIM; k += 4) {
            a0 = fmaf(fr[k + 0], wcol[k + 0], a0);
            a1 = fmaf(fr[k + 1], wcol[k + 1], a1);
            a2 = fmaf(fr[k + 2], wcol[k + 2], a2);
            a3 = fmaf(fr[k + 3], wcol[k + 3], a3);
        }
        g_G[(size_t)(row0 + r) * CDIM + d] = (a0 + a1) + (a2 + a3);
    }
}

// ---------------------------------------------------------------------------
__device__ __forceinline__ void ins3(float s, int idx,
                                     float& d0, float& d1, float& d2,
                                     int& i0, int& i1, int& i2)
{
    if (s < d2) {
        if (s < d1) {
            d2 = d1; i2 = i1;
            if (s < d0) { d1 = d0; i1 = i0; d0 = s; i0 = idx; }
            else        { d1 = s;  i1 = idx; }
        } else {
            d2 = s; i2 = idx;
        }
    }
}

// ---------------------------------------------------------------------------
// K5: thread-per-query 3-NN over SORTED queries.
//  - analytic Gaussian-density starting radius r0 (stop rule stays exact)
//  - row ranges loaded in batches of 8 (MLP) before scanning points
// ---------------------------------------------------------------------------
#define RB 8

__global__ __launch_bounds__(256) void query_kernel()
{
    const int t = blockIdx.x * 256 + threadIdx.x;     // sorted order
    const float4 qp = g_sqpos[t];
    const int qid = g_sqid[t];
    const int b = qid >> 14;

    const float qx = qp.x, qy = qp.y, qz = qp.z, qn = qp.w;
    const float qx2 = -2.0f * qx, qy2 = -2.0f * qy, qz2 = -2.0f * qz;
    const int cx = cell_coord(qx), cy = cell_coord(qy), cz = cell_coord(qz);

    // analytic starting radius from Gaussian density (hint only; exactness
    // comes from the face-distance stop rule below)
    float rho = 260.8f * __expf(-0.5f * qn);
    float d3e = cbrtf(0.7162f / rho);
    int r = max(1, min(GDIM, (int)ceilf(d3e * 1.35f * GINV)));

    float d0, d1, d2;
    int   i0 = 0, i1 = 0, i2 = 0;

    while (true) {
        d0 = FLT_MAX; d1 = FLT_MAX; d2 = FLT_MAX;
        const int xlo = max(cx - r, 0), xhi = min(cx + r, GDIM - 1);
        const int ylo = max(cy - r, 0), yhi = min(cy + r, GDIM - 1);
        const int zlo = max(cz - r, 0), zhi = min(cz + r, GDIM - 1);
        const int ny = yhi - ylo + 1;
        const int nrows = (zhi - zlo + 1) * ny;

        int zc = zlo, yc = ylo;        // row cursor
        for (int base = 0; base < nrows; base += RB) {
            int rs[RB], re[RB];
            const int cnt = min(RB, nrows - base);
#pragma unroll
            for (int k = 0; k < RB; k++) {
                if (k < cnt) {
                    const int row = b * GCELLS + ((zc * GDIM) + yc) * GDIM;
                    rs[k] = __ldg(&g_start2[0][row + xlo]);
                    re[k] = __ldg(&g_start2[0][row + xhi + 1]);
                    if (++yc > yhi) { yc = ylo; zc++; }
                } else { rs[k] = 0; re[k] = 0; }
            }
#pragma unroll
            for (int k = 0; k < RB; k++) {
                for (int i = rs[k]; i < re[k]; i++) {
                    float4 p = __ldg(&g_spos[i]);
                    float sv = fmaf(qx2, p.x, fmaf(qy2, p.y, fmaf(qz2, p.z, p.w)));
                    if (sv < d2) ins3(sv, i, d0, d1, d2, i0, i1, i2);
                }
            }
        }

        // exact stop: 3rd-NN true dist within distance to nearest unclipped face
        float rb = FLT_MAX;
        bool covered = true;
        if (cx - r > 0)        { rb = fminf(rb, qx - (GLO + (cx - r) * GH));     covered = false; }
        if (cx + r < GDIM - 1) { rb = fminf(rb, (GLO + (cx + r + 1) * GH) - qx); covered = false; }
        if (cy - r > 0)        { rb = fminf(rb, qy - (GLO + (cy - r) * GH));     covered = false; }
        if (cy + r < GDIM - 1) { rb = fminf(rb, (GLO + (cy + r + 1) * GH) - qy); covered = false; }
        if (cz - r > 0)        { rb = fminf(rb, qz - (GLO + (cz - r) * GH));     covered = false; }
        if (cz + r < GDIM - 1) { rb = fminf(rb, (GLO + (cz + r + 1) * GH) - qz); covered = false; }

        if (covered) break;
        if (d2 + qn <= rb * rb * 0.99999f) break;
        r++;
    }

    float w0 = 1.0f / ((d0 + qn) + EPSV);
    float w1 = 1.0f / ((d1 + qn) + EPSV);
    float w2 = 1.0f / ((d2 + qn) + EPSV);
    float inv = 1.0f / (w0 + w1 + w2);
    g_w3[qid] = make_float4(w0 * inv, w1 * inv, w2 * inv, 0.f);
    g_j3[qid] = make_int4(g_sidx[i0], g_sidx[i1], g_sidx[i2], 0);
}

// ---------------------------------------------------------------------------
// K6: apply — 4 threads per query, coalesced blend of 3 G rows + ReLU
// ---------------------------------------------------------------------------
__global__ __launch_bounds__(256) void apply_kernel(float* __restrict__ out)
{
    const int t = blockIdx.x * 256 + threadIdx.x;    // 262144 threads
    const int q = t >> 2;
    const int sub = t & 3;
    const int b = q >> 14;

    const float4 w = g_w3[q];
    const int4   j = g_j3[q];

    const float4* G4 = reinterpret_cast<const float4*>(g_G);
    const float4* r0 = G4 + (size_t)(b * NPTS + j.x) * (CDIM / 4) + sub * 4;
    const float4* r1 = G4 + (size_t)(b * NPTS + j.y) * (CDIM / 4) + sub * 4;
    const float4* r2 = G4 + (size_t)(b * NPTS + j.z) * (CDIM / 4) + sub * 4;
    float4* out4 = reinterpret_cast<float4*>(out) + (size_t)q * (CDIM / 4) + sub * 4;

#pragma unroll
    for (int k = 0; k < 4; k++) {
        float4 a = __ldg(&r0[k]);
        float4 c = __ldg(&r1[k]);
        float4 e = __ldg(&r2[k]);
        float4 o;
        o.x = fmaxf(0.f, fmaf(w.x, a.x, fmaf(w.y, c.x, w.z * e.x)));
        o.y = fmaxf(0.f, fmaf(w.x, a.y, fmaf(w.y, c.y, w.z * e.y)));
        o.z = fmaxf(0.f, fmaf(w.x, a.z, fmaf(w.y, c.z, w.z * e.z)));
        o.w = fmaxf(0.f, fmaf(w.x, a.w, fmaf(w.y, c.w, w.z * e.w)));
        out4[k] = o;
    }
}

// ---------------------------------------------------------------------------
extern "C" void kernel_launch(void* const* d_in, const int* in_sizes, int n_in,
                              void* d_out, int out_size)
{
    const float* feature = (const float*)d_in[0];   // (4, 4096, 64)
    const float* pos     = (const float*)d_in[1];   // (4, 4096, 3)
    const float* pos_up  = (const float*)d_in[2];   // (4, 16384, 3)
    const float* W       = (const float*)d_in[3];   // (64, 64)
    const float* bias    = (const float*)d_in[4];   // (64,)
    float* out = (float*)d_out;                     // (4, 16384, 64)

    zero_cnt_kernel<<<500, 256>>>();
    hist_both_kernel<<<320, 256>>>(pos, pos_up);
    proj_kernel<<<BATCH * NPTS / PROJ_ROWS, 64>>>(feature, W, bias);
    scan_a_kernel<<<2 * SCANB, 1024>>>();
    scan_b_kernel<<<2, 1024>>>();
    scan_c_kernel<<<2 * SCANB, 1024>>>();
    scatter_both_kernel<<<320, 256>>>();

    query_kernel<<<BATCH * NUP / 256, 256>>>();

    apply_kernel<<<BATCH * NUP * 4 / 256, 256>>>(out);
}

// round 9
// speedup vs baseline: 9.2882x; 9.2882x over previous
#include <cuda_runtime.h>
#include <cuda_bf16.h>
#include <cfloat>

#define BATCH 4
#define NPTS 4096
#define NUP 16384
#define CDIM 64
#define EPSV 1e-6f

// Spatial grid: [-4,4]^3, h=0.25
#define GDIM 32
#define GCELLS (GDIM * GDIM * GDIM)     // 32768
#define TOTCELLS (BATCH * GCELLS)       // 131072
#define GLO (-4.0f)
#define GH 0.25f
#define GINV 4.0f
#define SCANB (TOTCELLS / 1024)         // 128

// Scratch (__device__ globals; no cudaMalloc allowed)
__device__ float  g_G[BATCH * NPTS * CDIM];     // projected features F@W+b (4 MB)
__device__ int    g_cnt2[2][TOTCELLS];          // histograms: [0]=points [1]=queries
__device__ int    g_start2[2][TOTCELLS + 1];    // exclusive scans
__device__ int    g_cur2[2][TOTCELLS];          // scatter cursors
__device__ int    g_bsum2[2][256];              // block sums
__device__ float4 g_tpos[BATCH * NPTS];
__device__ int    g_tcell[BATCH * NPTS];
__device__ float4 g_qpos[BATCH * NUP];
__device__ int    g_qcell[BATCH * NUP];
__device__ float4 g_spos[BATCH * NPTS];         // cell-sorted points
__device__ int    g_sidx[BATCH * NPTS];         // sorted -> original local idx
__device__ float4 g_sqpos[BATCH * NUP];         // cell-sorted queries
__device__ int    g_sqid[BATCH * NUP];          // sorted -> original global qid
__device__ float4 g_w3[BATCH * NUP];            // normalized weights (by orig qid)
__device__ int4   g_j3[BATCH * NUP];            // neighbor orig indices (by orig qid)

__device__ __forceinline__ int cell_coord(float v) {
    int c = (int)floorf((v - GLO) * GINV);
    return min(max(c, 0), GDIM - 1);
}

// ---------------------------------------------------------------------------
// K0: zero both histograms (2*TOTCELLS ints = 65536 int4)
// ---------------------------------------------------------------------------
__global__ void zero_cnt_kernel() {
    int i = blockIdx.x * blockDim.x + threadIdx.x;     // 65536 threads
    reinterpret_cast<int4*>(&g_cnt2[0][0])[i] = make_int4(0, 0, 0, 0);
}

// ---------------------------------------------------------------------------
// K1: histogram + stage for BOTH points (blocks [0,64)) and queries [64,320)
// ---------------------------------------------------------------------------
__global__ void hist_both_kernel(const float* __restrict__ pos,
                                 const float* __restrict__ pos_up) {
    int t = blockIdx.x * 256 + threadIdx.x;
    if (blockIdx.x < 64) {                 // points
        int i = t;
        int b = i >> 12;
        float x = pos[3 * i + 0];
        float y = pos[3 * i + 1];
        float z = pos[3 * i + 2];
        float n = x * x + y * y + z * z;
        g_tpos[i] = make_float4(x, y, z, n);
        int cell = b * GCELLS + ((cell_coord(z) * GDIM) + cell_coord(y)) * GDIM + cell_coord(x);
        g_tcell[i] = cell;
        atomicAdd(&g_cnt2[0][cell], 1);
    } else {                               // queries
        int i = t - 16384;
        int b = i >> 14;
        float x = pos_up[3 * i + 0];
        float y = pos_up[3 * i + 1];
        float z = pos_up[3 * i + 2];
        float n = x * x + y * y + z * z;
        g_qpos[i] = make_float4(x, y, z, n);
        int cell = b * GCELLS + ((cell_coord(z) * GDIM) + cell_coord(y)) * GDIM + cell_coord(x);
        g_qcell[i] = cell;
        atomicAdd(&g_cnt2[1][cell], 1);
    }
}

// ---------------------------------------------------------------------------
// K2a/b/c: exclusive scans of both histograms
// ---------------------------------------------------------------------------
__device__ __forceinline__ int block_exscan_1024(int v, int* ws) {
    int lane = threadIdx.x & 31, w = threadIdx.x >> 5;
    int inc = v;
#pragma unroll
    for (int o = 1; o < 32; o <<= 1) {
        int n = __shfl_up_sync(0xffffffffu, inc, o);
        if (lane >= o) inc += n;
    }
    if (lane == 31) ws[w] = inc;
    __syncthreads();
    if (w == 0) {
        int t = ws[lane];
#pragma unroll
        for (int o = 1; o < 32; o <<= 1) {
            int n = __shfl_up_sync(0xffffffffu, t, o);
            if (lane >= o) t += n;
        }
        ws[lane] = t;
    }
    __syncthreads();
    return inc - v + (w > 0 ? ws[w - 1] : 0);
}

__global__ __launch_bounds__(1024) void scan_a_kernel() {   // grid 2*SCANB
    __shared__ int ws[32];
    int ab = blockIdx.x >= SCANB;
    int blk = blockIdx.x - ab * SCANB;
    int g = blk * 1024 + threadIdx.x;
    int v = g_cnt2[ab][g];
    int ex = block_exscan_1024(v, ws);
    g_start2[ab][g] = ex;
    if (threadIdx.x == 1023) g_bsum2[ab][blk] = ex + v;
}

__global__ __launch_bounds__(1024) void scan_b_kernel() {   // grid 2
    __shared__ int ws[32];
    int ab = blockIdx.x;
    int v = (threadIdx.x < SCANB) ? g_bsum2[ab][threadIdx.x] : 0;
    int ex = block_exscan_1024(v, ws);
    if (threadIdx.x < SCANB) g_bsum2[ab][threadIdx.x] = ex;
}

__global__ __launch_bounds__(1024) void scan_c_kernel() {   // grid 2*SCANB
    int ab = blockIdx.x >= SCANB;
    int blk = blockIdx.x - ab * SCANB;
    int g = blk * 1024 + threadIdx.x;
    int s = g_start2[ab][g] + g_bsum2[ab][blk];
    g_start2[ab][g] = s;
    g_cur2[ab][g] = s;
    if (g == TOTCELLS - 1)
        g_start2[ab][TOTCELLS] = ab ? (BATCH * NUP) : (BATCH * NPTS);
}

// ---------------------------------------------------------------------------
// K3: scatter both into cell-sorted order
// ---------------------------------------------------------------------------
__global__ void scatter_both_kernel() {
    int t = blockIdx.x * 256 + threadIdx.x;
    if (blockIdx.x < 64) {
        int i = t;
        int dst = atomicAdd(&g_cur2[0][g_tcell[i]], 1);
        g_spos[dst] = g_tpos[i];
        g_sidx[dst] = i & (NPTS - 1);
    } else {
        int i = t - 16384;
        int dst = atomicAdd(&g_cur2[1][g_qcell[i]], 1);
        g_sqpos[dst] = g_qpos[i];
        g_sqid[dst] = i;
    }
}

// ---------------------------------------------------------------------------
// K4: projection G = F @ W + b
// ---------------------------------------------------------------------------
#define PROJ_ROWS 32

__global__ __launch_bounds__(64) void proj_kernel(
    const float* __restrict__ feature,
    const float* __restrict__ W,
    const float* __restrict__ bias)
{
    __shared__ float frow[PROJ_ROWS * CDIM];
    const int d = threadIdx.x;
    const int row0 = blockIdx.x * PROJ_ROWS;

    float wcol[CDIM];
#pragma unroll
    for (int k = 0; k < CDIM; k++) wcol[k] = __ldg(&W[k * CDIM + d]);
    const float bd = __ldg(&bias[d]);

    const float* fsrc = feature + (size_t)row0 * CDIM;
    for (int i = threadIdx.x; i < PROJ_ROWS * CDIM; i += 64)
        frow[i] = fsrc[i];
    __syncthreads();

    for (int r = 0; r < PROJ_ROWS; r++) {
        float a0 = bd, a1 = 0.f, a2 = 0.f, a3 = 0.f;
        const float* fr = &frow[r * CDIM];
#pragma unroll
        for (int k = 0; k < CDIM; k += 4) {
            a0 = fmaf(fr[k + 0], wcol[k + 0], a0);
            a1 = fmaf(fr[k + 1], wcol[k + 1], a1);
            a2 = fmaf(fr[k + 2], wcol[k + 2], a2);
            a3 = fmaf(fr[k + 3], wcol[k + 3], a3);
        }
        g_G[(size_t)(row0 + r) * CDIM + d] = (a0 + a1) + (a2 + a3);
    }
}

// ---------------------------------------------------------------------------
__device__ __forceinline__ void ins3(float s, int idx,
                                     float& d0, float& d1, float& d2,
                                     int& i0, int& i1, int& i2)
{
    if (s < d2) {
        if (s < d1) {
            d2 = d1; i2 = i1;
            if (s < d0) { d1 = d0; i1 = i0; d0 = s; i0 = idx; }
            else        { d1 = s;  i1 = idx; }
        } else {
            d2 = s; i2 = idx;
        }
    }
}

// ---------------------------------------------------------------------------
// K5: 4-threads-per-query 3-NN over SORTED queries.
// Warp = 8 queries x 4 subs; sub scans rows ridx % 4 == sub of the cube.
// Merge across subs = 2 butterfly shfl rounds. Expansion = reset + rescan
// (exact face-distance stop rule). Done lanes keep shuffling, never update.
// ---------------------------------------------------------------------------
#define RB 4

__global__ __launch_bounds__(256, 4) void query_kernel()
{
    const int lane = threadIdx.x & 31;
    const int warp = threadIdx.x >> 5;
    const int sub  = lane >> 3;          // 0..3
    const int qi   = lane & 7;           // 0..7
    const int t = blockIdx.x * 64 + warp * 8 + qi;   // sorted query index
    const float4 qp = __ldg(&g_sqpos[t]);
    const int qid = __ldg(&g_sqid[t]);
    const int b = qid >> 14;

    const float qx = qp.x, qy = qp.y, qz = qp.z, qn = qp.w;
    const float qx2 = -2.0f * qx, qy2 = -2.0f * qy, qz2 = -2.0f * qz;
    const int cx = cell_coord(qx), cy = cell_coord(qy), cz = cell_coord(qz);

    float d0 = FLT_MAX, d1 = FLT_MAX, d2 = FLT_MAX;
    int   i0 = 0, i1 = 0, i2 = 0;

    int r = 1;
    bool done = false;

    while (true) {
        if (!done) {
            d0 = FLT_MAX; d1 = FLT_MAX; d2 = FLT_MAX;
            const int xlo = max(cx - r, 0), xhi = min(cx + r, GDIM - 1);
            const int ylo = max(cy - r, 0), yhi = min(cy + r, GDIM - 1);
            const int zlo = max(cz - r, 0), zhi = min(cz + r, GDIM - 1);
            const int ny = yhi - ylo + 1;
            const int nrows = (zhi - zlo + 1) * ny;

            for (int base = sub; base < nrows; base += 4 * RB) {
                int rs[RB], re[RB];
#pragma unroll
                for (int k = 0; k < RB; k++) {
                    const int ridx = base + k * 4;
                    if (ridx < nrows) {
                        const int zz = zlo + ridx / ny;
                        const int yy = ylo + (ridx - (ridx / ny) * ny);
                        const int row = b * GCELLS + ((zz * GDIM) + yy) * GDIM;
                        rs[k] = __ldg(&g_start2[0][row + xlo]);
                        re[k] = __ldg(&g_start2[0][row + xhi + 1]);
                    } else { rs[k] = 0; re[k] = 0; }
                }
#pragma unroll
                for (int k = 0; k < RB; k++) {
                    for (int i = rs[k]; i < re[k]; i++) {
                        float4 p = __ldg(&g_spos[i]);
                        float sv = fmaf(qx2, p.x, fmaf(qy2, p.y, fmaf(qz2, p.z, p.w)));
                        if (sv < d2) ins3(sv, i, d0, d1, d2, i0, i1, i2);
                    }
                }
            }
        }

        // merge across 4 subs (all lanes participate in shuffles)
#pragma unroll
        for (int off = 8; off <= 16; off <<= 1) {
            float e0 = __shfl_xor_sync(0xffffffffu, d0, off);
            float e1 = __shfl_xor_sync(0xffffffffu, d1, off);
            float e2 = __shfl_xor_sync(0xffffffffu, d2, off);
            int   f0 = __shfl_xor_sync(0xffffffffu, i0, off);
            int   f1 = __shfl_xor_sync(0xffffffffu, i1, off);
            int   f2 = __shfl_xor_sync(0xffffffffu, i2, off);
            if (!done) {
                ins3(e0, f0, d0, d1, d2, i0, i1, i2);
                ins3(e1, f1, d0, d1, d2, i0, i1, i2);
                ins3(e2, f2, d0, d1, d2, i0, i1, i2);
            }
        }

        if (!done) {
            // exact stop: 3rd-NN true dist within distance to nearest unclipped face
            float rb = FLT_MAX;
            bool covered = true;
            if (cx - r > 0)        { rb = fminf(rb, qx - (GLO + (cx - r) * GH));     covered = false; }
            if (cx + r < GDIM - 1) { rb = fminf(rb, (GLO + (cx + r + 1) * GH) - qx); covered = false; }
            if (cy - r > 0)        { rb = fminf(rb, qy - (GLO + (cy - r) * GH));     covered = false; }
            if (cy + r < GDIM - 1) { rb = fminf(rb, (GLO + (cy + r + 1) * GH) - qy); covered = false; }
            if (cz - r > 0)        { rb = fminf(rb, qz - (GLO + (cz - r) * GH));     covered = false; }
            if (cz + r < GDIM - 1) { rb = fminf(rb, (GLO + (cz + r + 1) * GH) - qz); covered = false; }

            done = covered || (d2 + qn <= rb * rb * 0.99999f);
            if (!done) r++;
        }
        if (__all_sync(0xffffffffu, done)) break;
    }

    if (sub == 0) {
        float w0 = 1.0f / ((d0 + qn) + EPSV);
        float w1 = 1.0f / ((d1 + qn) + EPSV);
        float w2 = 1.0f / ((d2 + qn) + EPSV);
        float inv = 1.0f / (w0 + w1 + w2);
        g_w3[qid] = make_float4(w0 * inv, w1 * inv, w2 * inv, 0.f);
        g_j3[qid] = make_int4(g_sidx[i0], g_sidx[i1], g_sidx[i2], 0);
    }
}

// ---------------------------------------------------------------------------
// K6: apply — 4 threads per query, coalesced blend of 3 G rows + ReLU
// ---------------------------------------------------------------------------
__global__ __launch_bounds__(256) void apply_kernel(float* __restrict__ out)
{
    const int t = blockIdx.x * 256 + threadIdx.x;    // 262144 threads
    const int q = t >> 2;
    const int sub = t & 3;
    const int b = q >> 14;

    const float4 w = g_w3[q];
    const int4   j = g_j3[q];

    const float4* G4 = reinterpret_cast<const float4*>(g_G);
    const float4* r0 = G4 + (size_t)(b * NPTS + j.x) * (CDIM / 4) + sub * 4;
    const float4* r1 = G4 + (size_t)(b * NPTS + j.y) * (CDIM / 4) + sub * 4;
    const float4* r2 = G4 + (size_t)(b * NPTS + j.z) * (CDIM / 4) + sub * 4;
    float4* out4 = reinterpret_cast<float4*>(out) + (size_t)q * (CDIM / 4) + sub * 4;

#pragma unroll
    for (int k = 0; k < 4; k++) {
        float4 a = __ldg(&r0[k]);
        float4 c = __ldg(&r1[k]);
        float4 e = __ldg(&r2[k]);
        float4 o;
        o.x = fmaxf(0.f, fmaf(w.x, a.x, fmaf(w.y, c.x, w.z * e.x)));
        o.y = fmaxf(0.f, fmaf(w.x, a.y, fmaf(w.y, c.y, w.z * e.y)));
        o.z = fmaxf(0.f, fmaf(w.x, a.z, fmaf(w.y, c.z, w.z * e.z)));
        o.w = fmaxf(0.f, fmaf(w.x, a.w, fmaf(w.y, c.w, w.z * e.w)));
        out4[k] = o;
    }
}

// ---------------------------------------------------------------------------
extern "C" void kernel_launch(void* const* d_in, const int* in_sizes, int n_in,
                              void* d_out, int out_size)
{
    const float* feature = (const float*)d_in[0];   // (4, 4096, 64)
    const float* pos     = (const float*)d_in[1];   // (4, 4096, 3)
    const float* pos_up  = (const float*)d_in[2];   // (4, 16384, 3)
    const float* W       = (const float*)d_in[3];   // (64, 64)
    const float* bias    = (const float*)d_in[4];   // (64,)
    float* out = (float*)d_out;                     // (4, 16384, 64)

    zero_cnt_kernel<<<256, 256>>>();
    hist_both_kernel<<<320, 256>>>(pos, pos_up);
    proj_kernel<<<BATCH * NPTS / PROJ_ROWS, 64>>>(feature, W, bias);
    scan_a_kernel<<<2 * SCANB, 1024>>>();
    scan_b_kernel<<<2, 1024>>>();
    scan_c_kernel<<<2 * SCANB, 1024>>>();
    scatter_both_kernel<<<320, 256>>>();

    query_kernel<<<BATCH * NUP / 64, 256>>>();

    apply_kernel<<<BATCH * NUP * 4 / 256, 256>>>(out);
}